// round 9
// baseline (speedup 1.0000x reference)
#include <cuda_runtime.h>
#include <cuda_bf16.h>
#include <cuda_fp16.h>
#include <math.h>
#include <cstdint>

#define NN 50000
#define EE 800000
#define DD 128
#define PAD 272                 // padded smem row stride (bytes): conflict-free ldmatrix
#define SA_H 0
#define SA_L 34816
#define SW_H 69632
#define SW_L 104448
#define SM_TOT 139264
#define CSR_G 148               // persistent CSR kernel grid (<= SM count)
#define CHUNK 1024

// ---- scratch (__device__ globals; allocation-free rule) ----
__device__ __half g_hwsh[(size_t)NN * DD];   // (h@W)*dinv, fp16 (gather payload)
__device__ float g_agg[(size_t)NN * DD];
__device__ int   g_count[NN];
__device__ float g_dinv[NN];
__device__ int   g_rowptr[NN + 1];
__device__ int   g_cursor[NN];
__device__ int   g_adj[EE];
__device__ int   g_partials[64];
__device__ __nv_bfloat16 g_wh[3 * DD * DD];  // W^T hi  ([n][k] row-major)
__device__ __nv_bfloat16 g_wl[3 * DD * DD];  // W^T lo
__device__ int   g_arrive;                   // grid barrier (zero-init; self-resets)
__device__ volatile int g_sense;             // generation (monotone across replays)

// ---- helpers ----
__device__ __forceinline__ uint32_t smem_u32(const void* p) {
    uint32_t a;
    asm("{ .reg .u64 t; cvta.to.shared.u64 t, %1; cvt.u32.u64 %0, t; }" : "=r"(a) : "l"(p));
    return a;
}
__device__ __forceinline__ void ldsm4(uint32_t* r, uint32_t addr) {
    asm volatile("ldmatrix.sync.aligned.m8n8.x4.shared.b16 {%0,%1,%2,%3}, [%4];"
                 : "=r"(r[0]), "=r"(r[1]), "=r"(r[2]), "=r"(r[3]) : "r"(addr));
}
__device__ __forceinline__ void mma_bf16(float* c, const uint32_t* a, uint32_t b0, uint32_t b1) {
    asm volatile("mma.sync.aligned.m16n8k16.row.col.f32.bf16.bf16.f32 "
                 "{%0,%1,%2,%3}, {%4,%5,%6,%7}, {%8,%9}, {%0,%1,%2,%3};"
                 : "+f"(c[0]), "+f"(c[1]), "+f"(c[2]), "+f"(c[3])
                 : "r"(a[0]), "r"(a[1]), "r"(a[2]), "r"(a[3]), "r"(b0), "r"(b1));
}
__device__ __forceinline__ void add8(float* a, uint4 v) {
    const __half2* h = reinterpret_cast<const __half2*>(&v);
#pragma unroll
    for (int i = 0; i < 4; i++) {
        float2 f = __half22float2(h[i]);
        a[2 * i] += f.x;
        a[2 * i + 1] += f.y;
    }
}

// Sense-reversal grid barrier (all CSR_G blocks participate, in order).
__device__ __forceinline__ void gridbar() {
    __syncthreads();
    if (threadIdx.x == 0) {
        int gen = g_sense;
        __threadfence();
        if (atomicAdd(&g_arrive, 1) == CSR_G - 1) {
            g_arrive = 0;
            __threadfence();
            g_sense = gen + 1;
        } else {
            while (g_sense == gen) __nanosleep(64);
        }
        __threadfence();
    }
    __syncthreads();
}

// ---------------------------------------------------------------------------
// Persistent CSR build + W split: one launch, 6 phases with grid barriers.
// ---------------------------------------------------------------------------
__global__ void __launch_bounds__(256, 1)
k_csr(const int* __restrict__ src, const int* __restrict__ dst,
      const float* __restrict__ W0, const float* __restrict__ W1,
      const float* __restrict__ W2, int n, int e) {
    const int tid = threadIdx.x;
    const int gtid = blockIdx.x * 256 + tid;
    const int gstride = CSR_G * 256;

    // P0: zero counts + W^T hi/lo split (independent work)
    for (int i = gtid; i < n; i += gstride) g_count[i] = 0;
    for (int gi = gtid; gi < 3 * DD * DD; gi += gstride) {
        int layer = gi >> 14, idx = gi & 16383;
        const float* W = (layer == 0) ? W0 : (layer == 1) ? W1 : W2;
        int k = idx >> 7, nn = idx & 127;
        float w = W[idx];
        __nv_bfloat16 h = __float2bfloat16(w);
        __nv_bfloat16 l = __float2bfloat16(w - __bfloat162float(h));
        g_wh[layer * DD * DD + nn * DD + k] = h;
        g_wl[layer * DD * DD + nn * DD + k] = l;
    }
    gridbar();

    // P1: count in-degrees
    for (int i = gtid; i < e; i += gstride) atomicAdd(&g_count[dst[i]], 1);
    gridbar();

    // P2: per-chunk scan (1024 elems / block; 4 per thread) + dinv
    {
        __shared__ int s[256];
        const int nchunks = (n + CHUNK - 1) / CHUNK;
        for (int c = blockIdx.x; c < nchunks; c += CSR_G) {
            int base = c * CHUNK + tid * 4;
            int v0 = 0, v1 = 0, v2 = 0, v3 = 0;
            if (base + 0 < n) { v0 = g_count[base + 0]; g_dinv[base + 0] = rsqrtf((float)v0 + 1.f); }
            if (base + 1 < n) { v1 = g_count[base + 1]; g_dinv[base + 1] = rsqrtf((float)v1 + 1.f); }
            if (base + 2 < n) { v2 = g_count[base + 2]; g_dinv[base + 2] = rsqrtf((float)v2 + 1.f); }
            if (base + 3 < n) { v3 = g_count[base + 3]; g_dinv[base + 3] = rsqrtf((float)v3 + 1.f); }
            int tsum = v0 + v1 + v2 + v3;
            s[tid] = tsum;
            __syncthreads();
#pragma unroll
            for (int off = 1; off < 256; off <<= 1) {
                int tmp = (tid >= off) ? s[tid - off] : 0;
                __syncthreads();
                s[tid] += tmp;
                __syncthreads();
            }
            int excl = s[tid] - tsum;
            if (base + 0 < n) g_rowptr[base + 0] = excl;
            if (base + 1 < n) g_rowptr[base + 1] = excl + v0;
            if (base + 2 < n) g_rowptr[base + 2] = excl + v0 + v1;
            if (base + 3 < n) g_rowptr[base + 3] = excl + v0 + v1 + v2;
            if (tid == 255) g_partials[c] = s[255];
            __syncthreads();
        }
    }
    gridbar();

    // P3: scan the (<=64) chunk partials — SINGLE WARP, shfl-based (no
    // __syncthreads in divergent code; the round-8 bug was exactly that).
    if (blockIdx.x == 0 && tid < 32) {
        const int nchunks = (n + CHUNK - 1) / CHUNK;
        int i2 = tid * 2;
        int v0 = (i2 < nchunks) ? g_partials[i2] : 0;
        int v1 = (i2 + 1 < nchunks) ? g_partials[i2 + 1] : 0;
        int ps = v0 + v1;
        int incl = ps;
#pragma unroll
        for (int off = 1; off < 32; off <<= 1) {
            int t = __shfl_up_sync(0xFFFFFFFFu, incl, off);
            if (tid >= off) incl += t;
        }
        int excl = incl - ps;
        if (i2 < nchunks) g_partials[i2] = excl;
        if (i2 + 1 < nchunks) g_partials[i2 + 1] = excl + v0;
    }
    gridbar();

    // P4: add chunk offsets; init cursors
    for (int i = gtid; i < n; i += gstride) {
        int r = g_rowptr[i] + g_partials[i / CHUNK];
        g_rowptr[i] = r;
        g_cursor[i] = r;
    }
    if (gtid == 0) g_rowptr[n] = e;
    gridbar();

    // P5: fill adjacency (grouped by dst)
    for (int i = gtid; i < e; i += gstride) {
        int pos = atomicAdd(&g_cursor[dst[i]], 1);
        g_adj[pos] = src[i];
    }
}

// ---------------------------------------------------------------------------
// Tensor-core GEMM (mma.sync bf16, 3-pass split, fp32 accum):
//   hwsh[row] = half((relu?(H[row]) @ W) * dinv[row])
// 256 threads / 8 warps; 128 rows per block; warp = 16 rows x 128 cols.
// ---------------------------------------------------------------------------
template <bool RELU>
__global__ void __launch_bounds__(256, 1)
k_gemm_mma(const float* __restrict__ H, const __nv_bfloat16* __restrict__ wth,
           const __nv_bfloat16* __restrict__ wtl, const float* __restrict__ dinv,
           __half* __restrict__ hws, int n) {
    extern __shared__ char smem[];
    const int tid = threadIdx.x;
    const int row0 = blockIdx.x * 128;

    {
        const float4* wh4 = reinterpret_cast<const float4*>(wth);
        const float4* wl4 = reinterpret_cast<const float4*>(wtl);
#pragma unroll
        for (int i = 0; i < 8; i++) {
            int chunk = i * 256 + tid;
            int r = chunk >> 4, c = chunk & 15;
            *reinterpret_cast<float4*>(smem + SW_H + r * PAD + c * 16) = wh4[chunk];
            *reinterpret_cast<float4*>(smem + SW_L + r * PAD + c * 16) = wl4[chunk];
        }
    }
    {
        const float4* H4 = reinterpret_cast<const float4*>(H);
#pragma unroll
        for (int i = 0; i < 16; i++) {
            int chunk = i * 256 + tid;
            int r = chunk >> 5, c = chunk & 31;
            int row = row0 + r;
            float4 v = make_float4(0.f, 0.f, 0.f, 0.f);
            if (row < n) v = H4[(size_t)row * 32 + c];
            if (RELU) {
                v.x = fmaxf(v.x, 0.f); v.y = fmaxf(v.y, 0.f);
                v.z = fmaxf(v.z, 0.f); v.w = fmaxf(v.w, 0.f);
            }
            __nv_bfloat162 h01 = __float22bfloat162_rn(make_float2(v.x, v.y));
            __nv_bfloat162 h23 = __float22bfloat162_rn(make_float2(v.z, v.w));
            float2 hf01 = __bfloat1622float2(h01);
            float2 hf23 = __bfloat1622float2(h23);
            __nv_bfloat162 l01 = __float22bfloat162_rn(make_float2(v.x - hf01.x, v.y - hf01.y));
            __nv_bfloat162 l23 = __float22bfloat162_rn(make_float2(v.z - hf23.x, v.w - hf23.y));
            uint2 hp, lp;
            hp.x = *reinterpret_cast<uint32_t*>(&h01);
            hp.y = *reinterpret_cast<uint32_t*>(&h23);
            lp.x = *reinterpret_cast<uint32_t*>(&l01);
            lp.y = *reinterpret_cast<uint32_t*>(&l23);
            *reinterpret_cast<uint2*>(smem + SA_H + r * PAD + c * 8) = hp;
            *reinterpret_cast<uint2*>(smem + SA_L + r * PAD + c * 8) = lp;
        }
    }
    __syncthreads();

    const uint32_t sb = smem_u32(smem);
    const int w = tid >> 5, lane = tid & 31;

    const uint32_t aAddrH = sb + SA_H +
        (uint32_t)(w * 16 + ((lane >> 3) & 1) * 8 + (lane & 7)) * PAD + (uint32_t)(lane >> 4) * 16;
    const uint32_t aAddrL = aAddrH + (SA_L - SA_H);
    const uint32_t bAddrH = sb + SW_H +
        (uint32_t)(((lane >> 4) & 1) * 8 + (lane & 7)) * PAD + (uint32_t)((lane >> 3) & 1) * 16;

    float c[16][4];
#pragma unroll
    for (int t = 0; t < 16; t++)
#pragma unroll
        for (int j = 0; j < 4; j++) c[t][j] = 0.f;

#pragma unroll
    for (int kk = 0; kk < 8; kk++) {
        uint32_t ah[4], al[4];
        ldsm4(ah, aAddrH + kk * 32);
        ldsm4(al, aAddrL + kk * 32);
#pragma unroll
        for (int np = 0; np < 8; np++) {
            uint32_t bh[4], bl[4];
            const uint32_t ba = bAddrH + (uint32_t)np * (16 * PAD) + kk * 32;
            ldsm4(bh, ba);
            ldsm4(bl, ba + (SW_L - SW_H));
            mma_bf16(c[np * 2 + 0], ah, bh[0], bh[1]);   // hi*hi
            mma_bf16(c[np * 2 + 1], ah, bh[2], bh[3]);
            mma_bf16(c[np * 2 + 0], ah, bl[0], bl[1]);   // hi*lo
            mma_bf16(c[np * 2 + 1], ah, bl[2], bl[3]);
            mma_bf16(c[np * 2 + 0], al, bh[0], bh[1]);   // lo*hi
            mma_bf16(c[np * 2 + 1], al, bh[2], bh[3]);
        }
    }

    const int g = lane >> 2, tg = lane & 3;
    const int rowA = row0 + w * 16 + g;
    const int rowB = rowA + 8;
    const float diA = (rowA < n) ? dinv[rowA] : 0.f;
    const float diB = (rowB < n) ? dinv[rowB] : 0.f;
#pragma unroll
    for (int t = 0; t < 16; t++) {
        const int col = t * 8 + tg * 2;
        if (rowA < n) {
            __half2 hv = __floats2half2_rn(c[t][0] * diA, c[t][1] * diA);
            *reinterpret_cast<__half2*>(hws + (size_t)rowA * DD + col) = hv;
        }
        if (rowB < n) {
            __half2 hv = __floats2half2_rn(c[t][2] * diB, c[t][3] * diB);
            *reinterpret_cast<__half2*>(hws + (size_t)rowB * DD + col) = hv;
        }
    }
}

// ---------------------------------------------------------------------------
// Pull-mode aggregate (fp16 gather, fp32 accumulate, 4-wide MLP batches):
//   out[d] = dinv[d]*(hws[d] + sum_{s in in(d)} hws[s]) + b (+x)
// Half-warp (16 lanes) per node; lane = uint4 (8 halves = 16B) slice.
// ---------------------------------------------------------------------------
template <bool ADDX>
__global__ void k_aggregate(const __half* __restrict__ hws, const int* __restrict__ rowptr,
                            const int* __restrict__ adj, const float* __restrict__ dinv,
                            const float* __restrict__ bias, const float* __restrict__ xres,
                            float* __restrict__ out, int n) {
    int w = (blockIdx.x * blockDim.x + threadIdx.x) >> 4;
    if (w >= n) return;
    const int lane = threadIdx.x & 15;

    const uint4* base = reinterpret_cast<const uint4*>(hws);  // 16 uint4 per row
    float acc0[8], acc1[8];
#pragma unroll
    for (int i = 0; i < 8; i++) { acc0[i] = 0.f; acc1[i] = 0.f; }
    add8(acc0, base[(size_t)w * 16 + lane]);  // self-loop

    int j = rowptr[w];
    const int jend = rowptr[w + 1];
    for (; j + 3 < jend; j += 4) {
        int s0 = __ldg(&adj[j]);
        int s1 = __ldg(&adj[j + 1]);
        int s2 = __ldg(&adj[j + 2]);
        int s3 = __ldg(&adj[j + 3]);
        uint4 a = base[(size_t)s0 * 16 + lane];
        uint4 b = base[(size_t)s1 * 16 + lane];
        uint4 c = base[(size_t)s2 * 16 + lane];
        uint4 d = base[(size_t)s3 * 16 + lane];
        add8(acc0, a); add8(acc1, b); add8(acc0, c); add8(acc1, d);
    }
    for (; j + 1 < jend; j += 2) {
        int s0 = __ldg(&adj[j]);
        int s1 = __ldg(&adj[j + 1]);
        uint4 a = base[(size_t)s0 * 16 + lane];
        uint4 b = base[(size_t)s1 * 16 + lane];
        add8(acc0, a); add8(acc1, b);
    }
    if (j < jend) add8(acc0, base[(size_t)__ldg(&adj[j]) * 16 + lane]);
#pragma unroll
    for (int i = 0; i < 8; i++) acc0[i] += acc1[i];

    const float di = dinv[w];
    const int col = lane * 8;
    float o[8];
#pragma unroll
    for (int i = 0; i < 8; i++) o[i] = fmaf(acc0[i], di, bias[col + i]);
    if (ADDX) {
        const float4* xr = reinterpret_cast<const float4*>(xres + (size_t)w * DD + col);
        float4 x0 = xr[0], x1 = xr[1];
        o[0] += x0.x; o[1] += x0.y; o[2] += x0.z; o[3] += x0.w;
        o[4] += x1.x; o[5] += x1.y; o[6] += x1.z; o[7] += x1.w;
    }
    float4* op = reinterpret_cast<float4*>(out + (size_t)w * DD + col);
    op[0] = make_float4(o[0], o[1], o[2], o[3]);
    op[1] = make_float4(o[4], o[5], o[6], o[7]);
}

// ---------------------------------------------------------------------------
extern "C" void kernel_launch(void* const* d_in, const int* in_sizes, int n_in,
                              void* d_out, int out_size) {
    const float* x  = (const float*)d_in[0];
    const int*   ei = (const int*)d_in[1];
    const float* W0 = (const float*)d_in[2];
    const float* b0 = (const float*)d_in[3];
    const float* W1 = (const float*)d_in[4];
    const float* b1 = (const float*)d_in[5];
    const float* W2 = (const float*)d_in[6];
    const float* b2 = (const float*)d_in[7];
    float* out = (float*)d_out;

    const int n = in_sizes[0] / DD;
    const int e = in_sizes[1] / 2;
    const int* src = ei;
    const int* dst = ei + e;

    float *d_agg, *d_dinv;
    __half* d_hws;
    int *d_rowptr, *d_adj;
    __nv_bfloat16 *d_wh, *d_wl;
    cudaGetSymbolAddress((void**)&d_hws, g_hwsh);
    cudaGetSymbolAddress((void**)&d_agg, g_agg);
    cudaGetSymbolAddress((void**)&d_dinv, g_dinv);
    cudaGetSymbolAddress((void**)&d_rowptr, g_rowptr);
    cudaGetSymbolAddress((void**)&d_adj, g_adj);
    cudaGetSymbolAddress((void**)&d_wh, g_wh);
    cudaGetSymbolAddress((void**)&d_wl, g_wl);

    cudaFuncSetAttribute(k_gemm_mma<false>, cudaFuncAttributeMaxDynamicSharedMemorySize, SM_TOT);
    cudaFuncSetAttribute(k_gemm_mma<true>,  cudaFuncAttributeMaxDynamicSharedMemorySize, SM_TOT);

    const int TB = 256;
    const int nb_gemm = (n + 127) / 128;
    const long long agg_threads = (long long)n * 16;
    const int nb_agg = (int)((agg_threads + TB - 1) / TB);

    // CSR build + dinv + W split: single persistent kernel
    k_csr<<<CSR_G, 256>>>(src, dst, W0, W1, W2, n, e);

    // Layer 0
    k_gemm_mma<false><<<nb_gemm, 256, SM_TOT>>>(x, d_wh, d_wl, d_dinv, d_hws, n);
    k_aggregate<false><<<nb_agg, TB>>>(d_hws, d_rowptr, d_adj, d_dinv, b0, nullptr, d_agg, n);
    // Layer 1
    k_gemm_mma<true><<<nb_gemm, 256, SM_TOT>>>(d_agg, d_wh + DD * DD, d_wl + DD * DD, d_dinv, d_hws, n);
    k_aggregate<false><<<nb_agg, TB>>>(d_hws, d_rowptr, d_adj, d_dinv, b1, nullptr, d_agg, n);
    // Layer 2 (+x residual, write d_out)
    k_gemm_mma<true><<<nb_gemm, 256, SM_TOT>>>(d_agg, d_wh + 2 * DD * DD, d_wl + 2 * DD * DD, d_dinv, d_hws, n);
    k_aggregate<true><<<nb_agg, TB>>>(d_hws, d_rowptr, d_adj, d_dinv, b2, x, out, n);
}

// round 11
// speedup vs baseline: 1.0245x; 1.0245x over previous
#include <cuda_runtime.h>
#include <cuda_bf16.h>
#include <cuda_fp16.h>
#include <math.h>
#include <cstdint>

#define NN 50000
#define EE 800000
#define DD 128
#define SCAN_B 1024
#define PAD 272                 // padded smem row stride (bytes): conflict-free ldmatrix
#define SW_H 0
#define SW_L 34816
#define SM_TOT 69632

// ---- scratch (__device__ globals; allocation-free rule) ----
__device__ __half g_hwsh[(size_t)NN * DD];   // (h@W)*dinv, fp16 (gather payload)
__device__ float g_agg[(size_t)NN * DD];
__device__ int   g_count[NN];
__device__ float g_dinv[NN];
__device__ int   g_rowptr[NN + 1];
__device__ int   g_cursor[NN];
__device__ int   g_adj[EE];
__device__ int   g_partials[64];
__device__ __nv_bfloat16 g_wh[3 * DD * DD];  // W^T hi  ([n][k] row-major)
__device__ __nv_bfloat16 g_wl[3 * DD * DD];  // W^T lo

// ---- helpers ----
__device__ __forceinline__ uint32_t smem_u32(const void* p) {
    uint32_t a;
    asm("{ .reg .u64 t; cvta.to.shared.u64 t, %1; cvt.u32.u64 %0, t; }" : "=r"(a) : "l"(p));
    return a;
}
__device__ __forceinline__ void ldsm4(uint32_t* r, uint32_t addr) {
    asm volatile("ldmatrix.sync.aligned.m8n8.x4.shared.b16 {%0,%1,%2,%3}, [%4];"
                 : "=r"(r[0]), "=r"(r[1]), "=r"(r[2]), "=r"(r[3]) : "r"(addr));
}
__device__ __forceinline__ void mma_bf16(float* c, const uint32_t* a, uint32_t b0, uint32_t b1) {
    asm volatile("mma.sync.aligned.m16n8k16.row.col.f32.bf16.bf16.f32 "
                 "{%0,%1,%2,%3}, {%4,%5,%6,%7}, {%8,%9}, {%0,%1,%2,%3};"
                 : "+f"(c[0]), "+f"(c[1]), "+f"(c[2]), "+f"(c[3])
                 : "r"(a[0]), "r"(a[1]), "r"(a[2]), "r"(a[3]), "r"(b0), "r"(b1));
}
__device__ __forceinline__ void add8(float* a, uint4 v) {
    const __half2* h = reinterpret_cast<const __half2*>(&v);
#pragma unroll
    for (int i = 0; i < 4; i++) {
        float2 f = __half22float2(h[i]);
        a[2 * i] += f.x;
        a[2 * i + 1] += f.y;
    }
}

// ---------------------------------------------------------------------------
// CSR build (by dst): count -> scan(+dinv) -> fill   (round-7 proven path)
// ---------------------------------------------------------------------------
__global__ void k_zero(int* c, int n) {
    int i = blockIdx.x * blockDim.x + threadIdx.x;
    if (i < n) c[i] = 0;
}
__global__ void k_count(const int* __restrict__ dst, int* __restrict__ count, int e) {
    int i = blockIdx.x * blockDim.x + threadIdx.x;
    if (i < e) atomicAdd(&count[dst[i]], 1);
}
__global__ void k_scan_chunks(const int* __restrict__ count, int* __restrict__ rowptr,
                              int* __restrict__ partials, float* __restrict__ dinv, int n) {
    __shared__ int s[SCAN_B];
    int t = threadIdx.x;
    int i = blockIdx.x * SCAN_B + t;
    int v = (i < n) ? count[i] : 0;
    if (i < n) dinv[i] = rsqrtf((float)v + 1.0f);
    s[t] = v;
    __syncthreads();
#pragma unroll
    for (int off = 1; off < SCAN_B; off <<= 1) {
        int tmp = (t >= off) ? s[t - off] : 0;
        __syncthreads();
        s[t] += tmp;
        __syncthreads();
    }
    if (i < n) rowptr[i] = s[t] - v;
    if (t == SCAN_B - 1) partials[blockIdx.x] = s[t];
}
__global__ void k_scan_partials(int* partials, int nchunks) {
    __shared__ int s[64];
    int t = threadIdx.x;
    int v = (t < nchunks) ? partials[t] : 0;
    s[t] = v;
    __syncthreads();
#pragma unroll
    for (int off = 1; off < 64; off <<= 1) {
        int tmp = (t >= off) ? s[t - off] : 0;
        __syncthreads();
        s[t] += tmp;
        __syncthreads();
    }
    if (t < nchunks) partials[t] = s[t] - v;
}
__global__ void k_scan_finish(int* __restrict__ rowptr, int* __restrict__ cursor,
                              const int* __restrict__ partials, int n, int e) {
    int i = blockIdx.x * blockDim.x + threadIdx.x;
    if (i < n) {
        int r = rowptr[i] + partials[i / SCAN_B];
        rowptr[i] = r;
        cursor[i] = r;
    }
    if (i == 0) rowptr[n] = e;
}
__global__ void k_fill(const int* __restrict__ src, const int* __restrict__ dst,
                       int* __restrict__ cursor, int* __restrict__ adj, int e) {
    int i = blockIdx.x * blockDim.x + threadIdx.x;
    if (i < e) {
        int pos = atomicAdd(&cursor[dst[i]], 1);
        adj[pos] = src[i];
    }
}

// ---------------------------------------------------------------------------
// W prep (all 3 layers): WT[n][k] = W[k][n], bf16 hi/lo split
// ---------------------------------------------------------------------------
__global__ void k_wsplit(const float* __restrict__ W0, const float* __restrict__ W1,
                         const float* __restrict__ W2, __nv_bfloat16* __restrict__ wh,
                         __nv_bfloat16* __restrict__ wl) {
    int gi = blockIdx.x * blockDim.x + threadIdx.x;  // < 3*16384
    int layer = gi >> 14, idx = gi & 16383;
    const float* W = (layer == 0) ? W0 : (layer == 1) ? W1 : W2;
    int k = idx >> 7, nn = idx & 127;
    float w = W[idx];
    __nv_bfloat16 h = __float2bfloat16(w);
    __nv_bfloat16 l = __float2bfloat16(w - __bfloat162float(h));
    wh[layer * DD * DD + nn * DD + k] = h;
    wl[layer * DD * DD + nn * DD + k] = l;
}

// ---------------------------------------------------------------------------
// Tensor-core GEMM (mma.sync bf16, 3-pass split, fp32 accum):
//   hwsh[row] = half((relu?(H[row]) @ W) * dinv[row])
// 256 threads / 8 warps; block tile 128x128; warp tile 32 rows x 64 cols
// (warp = mg(row-group 0..3) x cg(col-group 0..1)).
// A fragments built in registers from global fp32 (no A smem, no A ldsm);
// B (W^T hi/lo) staged once in smem, each B fragment reused by 2 m-sets.
// ---------------------------------------------------------------------------
template <bool RELU>
__global__ void __launch_bounds__(256, 2)
k_gemm_mma(const float* __restrict__ H, const __nv_bfloat16* __restrict__ wth,
           const __nv_bfloat16* __restrict__ wtl, const float* __restrict__ dinv,
           __half* __restrict__ hws, int n) {
    extern __shared__ char smem[];
    const int tid = threadIdx.x;
    const int row0 = blockIdx.x * 128;

    // Stage W^T hi/lo into padded smem
    {
        const float4* wh4 = reinterpret_cast<const float4*>(wth);
        const float4* wl4 = reinterpret_cast<const float4*>(wtl);
#pragma unroll
        for (int i = 0; i < 8; i++) {
            int chunk = i * 256 + tid;           // 2048 chunks of 16B
            int r = chunk >> 4, c = chunk & 15;
            *reinterpret_cast<float4*>(smem + SW_H + r * PAD + c * 16) = wh4[chunk];
            *reinterpret_cast<float4*>(smem + SW_L + r * PAD + c * 16) = wl4[chunk];
        }
    }
    __syncthreads();

    const uint32_t sb = smem_u32(smem);
    const int w = tid >> 5, lane = tid & 31;
    const int mg = w >> 1, cg = w & 1;
    const int g = lane >> 2, tg = lane & 3;

    // B ldmatrix per-lane base (n-row = cg*64 + sub, k-halves via 16B col sel)
    const uint32_t bAddrH = sb + SW_H +
        (uint32_t)(cg * 64 + ((lane >> 4) & 1) * 8 + (lane & 7)) * PAD +
        (uint32_t)((lane >> 3) & 1) * 16;

    const int rbase = row0 + mg * 32 + g;   // rows: rbase + ms*16 + {0,8}

    float acc[16][4];                       // [ms*8 + np*2 + h][4]
#pragma unroll
    for (int t = 0; t < 16; t++)
#pragma unroll
        for (int j = 0; j < 4; j++) acc[t][j] = 0.f;

#pragma unroll
    for (int kk = 0; kk < 8; kk++) {
        const int kb = kk * 16 + 2 * tg;
        uint32_t ah[2][4], al[2][4];
#pragma unroll
        for (int ms = 0; ms < 2; ms++) {
#pragma unroll
            for (int p = 0; p < 4; p++) {   // frag reg p: row +{0,8}[p&1], k +{0,8}[p>>1]
                int row = rbase + ms * 16 + (p & 1) * 8;
                float2 v = make_float2(0.f, 0.f);
                if (row < n)
                    v = *reinterpret_cast<const float2*>(H + (size_t)row * DD + kb + (p >> 1) * 8);
                if (RELU) { v.x = fmaxf(v.x, 0.f); v.y = fmaxf(v.y, 0.f); }
                __nv_bfloat162 h2 = __float22bfloat162_rn(v);
                float2 hf = __bfloat1622float2(h2);
                __nv_bfloat162 l2 = __float22bfloat162_rn(make_float2(v.x - hf.x, v.y - hf.y));
                ah[ms][p] = *reinterpret_cast<uint32_t*>(&h2);
                al[ms][p] = *reinterpret_cast<uint32_t*>(&l2);
            }
        }
#pragma unroll
        for (int np = 0; np < 4; np++) {
            uint32_t bh[4], bl[4];
            const uint32_t ba = bAddrH + (uint32_t)np * (16 * PAD) + kk * 32;
            ldsm4(bh, ba);
            ldsm4(bl, ba + (SW_L - SW_H));
#pragma unroll
            for (int ms = 0; ms < 2; ms++) {
                float* c0 = acc[ms * 8 + np * 2 + 0];
                float* c1 = acc[ms * 8 + np * 2 + 1];
                mma_bf16(c0, ah[ms], bh[0], bh[1]);   // hi*hi
                mma_bf16(c1, ah[ms], bh[2], bh[3]);
                mma_bf16(c0, ah[ms], bl[0], bl[1]);   // hi*lo
                mma_bf16(c1, ah[ms], bl[2], bl[3]);
                mma_bf16(c0, al[ms], bh[0], bh[1]);   // lo*hi
                mma_bf16(c1, al[ms], bh[2], bh[3]);
            }
        }
    }

    // Epilogue: scale by dinv, store fp16
#pragma unroll
    for (int ms = 0; ms < 2; ms++) {
        const int rA = rbase + ms * 16;
        const int rB = rA + 8;
        const float diA = (rA < n) ? dinv[rA] : 0.f;
        const float diB = (rB < n) ? dinv[rB] : 0.f;
#pragma unroll
        for (int np = 0; np < 4; np++) {
#pragma unroll
            for (int h = 0; h < 2; h++) {
                const float* cf = acc[ms * 8 + np * 2 + h];
                const int col = cg * 64 + np * 16 + h * 8 + tg * 2;
                if (rA < n) {
                    __half2 hv = __floats2half2_rn(cf[0] * diA, cf[1] * diA);
                    *reinterpret_cast<__half2*>(hws + (size_t)rA * DD + col) = hv;
                }
                if (rB < n) {
                    __half2 hv = __floats2half2_rn(cf[2] * diB, cf[3] * diB);
                    *reinterpret_cast<__half2*>(hws + (size_t)rB * DD + col) = hv;
                }
            }
        }
    }
}

// ---------------------------------------------------------------------------
// Pull-mode aggregate (fp16 gather, fp32 accumulate, 4-wide MLP batches):
//   out[d] = dinv[d]*(hws[d] + sum_{s in in(d)} hws[s]) + b (+x)
// Half-warp (16 lanes) per node; lane = uint4 (8 halves = 16B) slice.
// ---------------------------------------------------------------------------
template <bool ADDX>
__global__ void k_aggregate(const __half* __restrict__ hws, const int* __restrict__ rowptr,
                            const int* __restrict__ adj, const float* __restrict__ dinv,
                            const float* __restrict__ bias, const float* __restrict__ xres,
                            float* __restrict__ out, int n) {
    int w = (blockIdx.x * blockDim.x + threadIdx.x) >> 4;
    if (w >= n) return;
    const int lane = threadIdx.x & 15;

    const uint4* base = reinterpret_cast<const uint4*>(hws);  // 16 uint4 per row
    float acc0[8], acc1[8];
#pragma unroll
    for (int i = 0; i < 8; i++) { acc0[i] = 0.f; acc1[i] = 0.f; }
    add8(acc0, base[(size_t)w * 16 + lane]);  // self-loop

    int j = rowptr[w];
    const int jend = rowptr[w + 1];
    for (; j + 3 < jend; j += 4) {
        int s0 = __ldg(&adj[j]);
        int s1 = __ldg(&adj[j + 1]);
        int s2 = __ldg(&adj[j + 2]);
        int s3 = __ldg(&adj[j + 3]);
        uint4 a = base[(size_t)s0 * 16 + lane];
        uint4 b = base[(size_t)s1 * 16 + lane];
        uint4 c = base[(size_t)s2 * 16 + lane];
        uint4 d = base[(size_t)s3 * 16 + lane];
        add8(acc0, a); add8(acc1, b); add8(acc0, c); add8(acc1, d);
    }
    for (; j + 1 < jend; j += 2) {
        int s0 = __ldg(&adj[j]);
        int s1 = __ldg(&adj[j + 1]);
        uint4 a = base[(size_t)s0 * 16 + lane];
        uint4 b = base[(size_t)s1 * 16 + lane];
        add8(acc0, a); add8(acc1, b);
    }
    if (j < jend) add8(acc0, base[(size_t)__ldg(&adj[j]) * 16 + lane]);
#pragma unroll
    for (int i = 0; i < 8; i++) acc0[i] += acc1[i];

    const float di = dinv[w];
    const int col = lane * 8;
    float o[8];
#pragma unroll
    for (int i = 0; i < 8; i++) o[i] = fmaf(acc0[i], di, bias[col + i]);
    if (ADDX) {
        const float4* xr = reinterpret_cast<const float4*>(xres + (size_t)w * DD + col);
        float4 x0 = xr[0], x1 = xr[1];
        o[0] += x0.x; o[1] += x0.y; o[2] += x0.z; o[3] += x0.w;
        o[4] += x1.x; o[5] += x1.y; o[6] += x1.z; o[7] += x1.w;
    }
    float4* op = reinterpret_cast<float4*>(out + (size_t)w * DD + col);
    op[0] = make_float4(o[0], o[1], o[2], o[3]);
    op[1] = make_float4(o[4], o[5], o[6], o[7]);
}

// ---------------------------------------------------------------------------
extern "C" void kernel_launch(void* const* d_in, const int* in_sizes, int n_in,
                              void* d_out, int out_size) {
    const float* x  = (const float*)d_in[0];
    const int*   ei = (const int*)d_in[1];
    const float* W0 = (const float*)d_in[2];
    const float* b0 = (const float*)d_in[3];
    const float* W1 = (const float*)d_in[4];
    const float* b1 = (const float*)d_in[5];
    const float* W2 = (const float*)d_in[6];
    const float* b2 = (const float*)d_in[7];
    float* out = (float*)d_out;

    const int n = in_sizes[0] / DD;
    const int e = in_sizes[1] / 2;
    const int* src = ei;
    const int* dst = ei + e;

    float *d_agg, *d_dinv;
    __half* d_hws;
    int *d_count, *d_rowptr, *d_cursor, *d_adj, *d_partials;
    __nv_bfloat16 *d_wh, *d_wl;
    cudaGetSymbolAddress((void**)&d_hws, g_hwsh);
    cudaGetSymbolAddress((void**)&d_agg, g_agg);
    cudaGetSymbolAddress((void**)&d_dinv, g_dinv);
    cudaGetSymbolAddress((void**)&d_count, g_count);
    cudaGetSymbolAddress((void**)&d_rowptr, g_rowptr);
    cudaGetSymbolAddress((void**)&d_cursor, g_cursor);
    cudaGetSymbolAddress((void**)&d_adj, g_adj);
    cudaGetSymbolAddress((void**)&d_partials, g_partials);
    cudaGetSymbolAddress((void**)&d_wh, g_wh);
    cudaGetSymbolAddress((void**)&d_wl, g_wl);

    cudaFuncSetAttribute(k_gemm_mma<false>, cudaFuncAttributeMaxDynamicSharedMemorySize, SM_TOT);
    cudaFuncSetAttribute(k_gemm_mma<true>,  cudaFuncAttributeMaxDynamicSharedMemorySize, SM_TOT);

    const int TB = 256;
    const int nb_n = (n + TB - 1) / TB;
    const int nb_e = (e + TB - 1) / TB;
    const int nb_gemm = (n + 127) / 128;
    const int nchunks = (n + SCAN_B - 1) / SCAN_B;
    const long long agg_threads = (long long)n * 16;
    const int nb_agg = (int)((agg_threads + TB - 1) / TB);

    // CSR build + dinv
    k_zero<<<nb_n, TB>>>(d_count, n);
    k_count<<<nb_e, TB>>>(dst, d_count, e);
    k_scan_chunks<<<nchunks, SCAN_B>>>(d_count, d_rowptr, d_partials, d_dinv, n);
    k_scan_partials<<<1, 64>>>(d_partials, nchunks);
    k_scan_finish<<<nb_n, TB>>>(d_rowptr, d_cursor, d_partials, n, e);
    k_fill<<<nb_e, TB>>>(src, dst, d_cursor, d_adj, e);

    // W^T hi/lo (all 3 layers, one launch)
    k_wsplit<<<192, 256>>>(W0, W1, W2, d_wh, d_wl);

    // Layer 0
    k_gemm_mma<false><<<nb_gemm, 256, SM_TOT>>>(x, d_wh, d_wl, d_dinv, d_hws, n);
    k_aggregate<false><<<nb_agg, TB>>>(d_hws, d_rowptr, d_adj, d_dinv, b0, nullptr, d_agg, n);
    // Layer 1
    k_gemm_mma<true><<<nb_gemm, 256, SM_TOT>>>(d_agg, d_wh + DD * DD, d_wl + DD * DD, d_dinv, d_hws, n);
    k_aggregate<false><<<nb_agg, TB>>>(d_hws, d_rowptr, d_adj, d_dinv, b1, nullptr, d_agg, n);
    // Layer 2 (+x residual, write d_out)
    k_gemm_mma<true><<<nb_gemm, 256, SM_TOT>>>(d_agg, d_wh + 2 * DD * DD, d_wl + 2 * DD * DD, d_dinv, d_hws, n);
    k_aggregate<true><<<nb_agg, TB>>>(d_hws, d_rowptr, d_adj, d_dinv, b2, x, out, n);
}

// round 13
// speedup vs baseline: 1.2569x; 1.2268x over previous
#include <cuda_runtime.h>
#include <cuda_fp16.h>
#include <math.h>
#include <cstdint>

#define NN 50000
#define EE 800000
#define DD 128
#define SCAN_B 1024
#define PAD 272                 // padded smem row stride (bytes): conflict-free ldmatrix
#define SA 0
#define SW 34816
#define SM_TOT 69632

// ---- scratch (__device__ globals; allocation-free rule) ----
__device__ __half g_hwsh[(size_t)NN * DD];   // (h@W)*dinv, fp16 (gather payload)
__device__ __half g_aggh[(size_t)NN * DD];   // relu(aggregate), fp16 (next-layer input)
__device__ int    g_count[NN];
__device__ float  g_dinv[NN];
__device__ int    g_rowptr[NN + 1];
__device__ int    g_cursor[NN];
__device__ int    g_adj[EE];
__device__ int    g_partials[64];
__device__ __half g_wt[3 * DD * DD];         // W^T fp16 ([n][k] row-major)

// ---- helpers ----
__device__ __forceinline__ uint32_t smem_u32(const void* p) {
    uint32_t a;
    asm("{ .reg .u64 t; cvta.to.shared.u64 t, %1; cvt.u32.u64 %0, t; }" : "=r"(a) : "l"(p));
    return a;
}
__device__ __forceinline__ void ldsm4(uint32_t* r, uint32_t addr) {
    asm volatile("ldmatrix.sync.aligned.m8n8.x4.shared.b16 {%0,%1,%2,%3}, [%4];"
                 : "=r"(r[0]), "=r"(r[1]), "=r"(r[2]), "=r"(r[3]) : "r"(addr));
}
__device__ __forceinline__ void mma_f16(float* c, const uint32_t* a, uint32_t b0, uint32_t b1) {
    asm volatile("mma.sync.aligned.m16n8k16.row.col.f32.f16.f16.f32 "
                 "{%0,%1,%2,%3}, {%4,%5,%6,%7}, {%8,%9}, {%0,%1,%2,%3};"
                 : "+f"(c[0]), "+f"(c[1]), "+f"(c[2]), "+f"(c[3])
                 : "r"(a[0]), "r"(a[1]), "r"(a[2]), "r"(a[3]), "r"(b0), "r"(b1));
}
__device__ __forceinline__ void add8(float* a, uint4 v) {
    const __half2* h = reinterpret_cast<const __half2*>(&v);
#pragma unroll
    for (int i = 0; i < 4; i++) {
        float2 f = __half22float2(h[i]);
        a[2 * i] += f.x;
        a[2 * i + 1] += f.y;
    }
}

// ---------------------------------------------------------------------------
// CSR build (by dst): count -> scan(+dinv) -> fill   (proven path)
// ---------------------------------------------------------------------------
__global__ void k_zero(int* c, int n) {
    int i = blockIdx.x * blockDim.x + threadIdx.x;
    if (i < n) c[i] = 0;
}
__global__ void k_count(const int* __restrict__ dst, int* __restrict__ count, int e) {
    int i = blockIdx.x * blockDim.x + threadIdx.x;
    if (i < e) atomicAdd(&count[dst[i]], 1);
}
__global__ void k_scan_chunks(const int* __restrict__ count, int* __restrict__ rowptr,
                              int* __restrict__ partials, float* __restrict__ dinv, int n) {
    __shared__ int s[SCAN_B];
    int t = threadIdx.x;
    int i = blockIdx.x * SCAN_B + t;
    int v = (i < n) ? count[i] : 0;
    if (i < n) dinv[i] = rsqrtf((float)v + 1.0f);
    s[t] = v;
    __syncthreads();
#pragma unroll
    for (int off = 1; off < SCAN_B; off <<= 1) {
        int tmp = (t >= off) ? s[t - off] : 0;
        __syncthreads();
        s[t] += tmp;
        __syncthreads();
    }
    if (i < n) rowptr[i] = s[t] - v;
    if (t == SCAN_B - 1) partials[blockIdx.x] = s[t];
}
__global__ void k_scan_partials(int* partials, int nchunks) {
    __shared__ int s[64];
    int t = threadIdx.x;
    int v = (t < nchunks) ? partials[t] : 0;
    s[t] = v;
    __syncthreads();
#pragma unroll
    for (int off = 1; off < 64; off <<= 1) {
        int tmp = (t >= off) ? s[t - off] : 0;
        __syncthreads();
        s[t] += tmp;
        __syncthreads();
    }
    if (t < nchunks) partials[t] = s[t] - v;
}
__global__ void k_scan_finish(int* __restrict__ rowptr, int* __restrict__ cursor,
                              const int* __restrict__ partials, int n, int e) {
    int i = blockIdx.x * blockDim.x + threadIdx.x;
    if (i < n) {
        int r = rowptr[i] + partials[i / SCAN_B];
        rowptr[i] = r;
        cursor[i] = r;
    }
    if (i == 0) rowptr[n] = e;
}
__global__ void k_fill(const int* __restrict__ src, const int* __restrict__ dst,
                       int* __restrict__ cursor, int* __restrict__ adj, int e) {
    int i = blockIdx.x * blockDim.x + threadIdx.x;
    if (i < e) {
        int pos = atomicAdd(&cursor[dst[i]], 1);
        adj[pos] = src[i];
    }
}

// ---------------------------------------------------------------------------
// W prep (all 3 layers): WT[n][k] = fp16(W[k][n])
// ---------------------------------------------------------------------------
__global__ void k_wprep(const float* __restrict__ W0, const float* __restrict__ W1,
                        const float* __restrict__ W2, __half* __restrict__ wt) {
    int gi = blockIdx.x * blockDim.x + threadIdx.x;  // < 3*16384
    int layer = gi >> 14, idx = gi & 16383;
    const float* W = (layer == 0) ? W0 : (layer == 1) ? W1 : W2;
    int k = idx >> 7, nn = idx & 127;
    wt[layer * DD * DD + nn * DD + k] = __float2half(W[idx]);
}

// ---------------------------------------------------------------------------
// Tensor-core GEMM (mma.sync fp16 single-pass, fp32 accum):
//   hwsh[row] = half((H[row] @ W) * dinv[row])
// 256 threads / 8 warps; block 128x128; warp tile 32 rows x 64 cols.
// A staged in smem fp16 (verbatim for fp16 input; cvt for fp32 layer-0 input).
// ---------------------------------------------------------------------------
template <bool INHALF>
__global__ void __launch_bounds__(256, 2)
k_gemm_mma(const float* __restrict__ Hf, const __half* __restrict__ Hh,
           const __half* __restrict__ wt, const float* __restrict__ dinv,
           __half* __restrict__ hws, int n) {
    extern __shared__ char smem[];
    const int tid = threadIdx.x;
    const int row0 = blockIdx.x * 128;

    // Stage W^T (fp16, 32KB) into padded smem
    {
        const float4* w4 = reinterpret_cast<const float4*>(wt);
#pragma unroll
        for (int i = 0; i < 8; i++) {
            int chunk = i * 256 + tid;           // 2048 chunks of 16B
            int r = chunk >> 4, c = chunk & 15;
            *reinterpret_cast<float4*>(smem + SW + r * PAD + c * 16) = w4[chunk];
        }
    }
    // Stage A (fp16) into padded smem
    if (INHALF) {
        const uint4* H4 = reinterpret_cast<const uint4*>(Hh);
        const int maxc = (n - row0) * 16;
#pragma unroll
        for (int i = 0; i < 8; i++) {
            int chunk = i * 256 + tid;           // 2048 chunks (128 rows x 16)
            int r = chunk >> 4, c = chunk & 15;
            uint4 v = make_uint4(0u, 0u, 0u, 0u);
            if (chunk < maxc) v = H4[(size_t)row0 * 16 + chunk];
            *reinterpret_cast<uint4*>(smem + SA + r * PAD + c * 16) = v;
        }
    } else {
        const float4* H4 = reinterpret_cast<const float4*>(Hf);
        const int maxc = (n - row0) * 32;
#pragma unroll
        for (int i = 0; i < 16; i++) {
            int chunk = i * 256 + tid;           // 4096 chunks (128 rows x 32)
            int r = chunk >> 5, c = chunk & 31;
            float4 v = make_float4(0.f, 0.f, 0.f, 0.f);
            if (chunk < maxc) v = H4[(size_t)row0 * 32 + chunk];
            __half2 h01 = __floats2half2_rn(v.x, v.y);
            __half2 h23 = __floats2half2_rn(v.z, v.w);
            uint2 hp;
            hp.x = *reinterpret_cast<uint32_t*>(&h01);
            hp.y = *reinterpret_cast<uint32_t*>(&h23);
            *reinterpret_cast<uint2*>(smem + SA + r * PAD + c * 8) = hp;
        }
    }
    __syncthreads();

    const uint32_t sb = smem_u32(smem);
    const int w = tid >> 5, lane = tid & 31;
    const int mg = w >> 1, cg = w & 1;
    const int g = lane >> 2, tg = lane & 3;

    const uint32_t aAddr = sb + SA +
        (uint32_t)(mg * 32 + (lane & 15)) * PAD + (uint32_t)(lane >> 4) * 16;
    const uint32_t bAddr = sb + SW +
        (uint32_t)(cg * 64 + ((lane >> 4) & 1) * 8 + (lane & 7)) * PAD +
        (uint32_t)((lane >> 3) & 1) * 16;

    float acc[16][4];                            // [ms*8 + np*2 + h][4]
#pragma unroll
    for (int t = 0; t < 16; t++)
#pragma unroll
        for (int j = 0; j < 4; j++) acc[t][j] = 0.f;

#pragma unroll
    for (int kk = 0; kk < 8; kk++) {
        uint32_t a0[4], a1[4];
        ldsm4(a0, aAddr + kk * 32);
        ldsm4(a1, aAddr + 16 * PAD + kk * 32);
#pragma unroll
        for (int np = 0; np < 4; np++) {
            uint32_t b[4];
            ldsm4(b, bAddr + (uint32_t)np * (16 * PAD) + kk * 32);
            mma_f16(acc[np * 2 + 0], a0, b[0], b[1]);
            mma_f16(acc[np * 2 + 1], a0, b[2], b[3]);
            mma_f16(acc[8 + np * 2 + 0], a1, b[0], b[1]);
            mma_f16(acc[8 + np * 2 + 1], a1, b[2], b[3]);
        }
    }

    // Epilogue: scale by dinv, store fp16
    const int rbase = row0 + mg * 32 + g;
#pragma unroll
    for (int ms = 0; ms < 2; ms++) {
        const int rA = rbase + ms * 16;
        const int rB = rA + 8;
        const float diA = (rA < n) ? dinv[rA] : 0.f;
        const float diB = (rB < n) ? dinv[rB] : 0.f;
#pragma unroll
        for (int np = 0; np < 4; np++) {
#pragma unroll
            for (int h = 0; h < 2; h++) {
                const float* cf = acc[ms * 8 + np * 2 + h];
                const int col = cg * 64 + np * 16 + h * 8 + tg * 2;
                if (rA < n) {
                    __half2 hv = __floats2half2_rn(cf[0] * diA, cf[1] * diA);
                    *reinterpret_cast<__half2*>(hws + (size_t)rA * DD + col) = hv;
                }
                if (rB < n) {
                    __half2 hv = __floats2half2_rn(cf[2] * diB, cf[3] * diB);
                    *reinterpret_cast<__half2*>(hws + (size_t)rB * DD + col) = hv;
                }
            }
        }
    }
}

// ---------------------------------------------------------------------------
// Pull-mode aggregate (fp16 gather, fp32 accumulate):
//   t = dinv[d]*(hws[d] + sum_{s in in(d)} hws[s]) + b
//   FINAL=0: outh[d] = fp16(relu(t))      (next layer's input)
//   FINAL=1: outf[d] = t + x[d]           (residual, fp32, d_out)
// Half-warp (16 lanes) per node; lane = uint4 (8 halves = 16B) slice.
// ---------------------------------------------------------------------------
template <bool FINAL>
__global__ void k_aggregate(const __half* __restrict__ hws, const int* __restrict__ rowptr,
                            const int* __restrict__ adj, const float* __restrict__ dinv,
                            const float* __restrict__ bias, const float* __restrict__ xres,
                            __half* __restrict__ outh, float* __restrict__ outf, int n) {
    int w = (blockIdx.x * blockDim.x + threadIdx.x) >> 4;
    if (w >= n) return;
    const int lane = threadIdx.x & 15;

    const uint4* base = reinterpret_cast<const uint4*>(hws);  // 16 uint4 per row
    float acc0[8], acc1[8];
#pragma unroll
    for (int i = 0; i < 8; i++) { acc0[i] = 0.f; acc1[i] = 0.f; }
    add8(acc0, base[(size_t)w * 16 + lane]);  // self-loop

    int j = rowptr[w];
    const int jend = rowptr[w + 1];
    for (; j + 3 < jend; j += 4) {
        int s0 = __ldg(&adj[j]);
        int s1 = __ldg(&adj[j + 1]);
        int s2 = __ldg(&adj[j + 2]);
        int s3 = __ldg(&adj[j + 3]);
        uint4 a = base[(size_t)s0 * 16 + lane];
        uint4 b = base[(size_t)s1 * 16 + lane];
        uint4 c = base[(size_t)s2 * 16 + lane];
        uint4 d = base[(size_t)s3 * 16 + lane];
        add8(acc0, a); add8(acc1, b); add8(acc0, c); add8(acc1, d);
    }
    for (; j + 1 < jend; j += 2) {
        int s0 = __ldg(&adj[j]);
        int s1 = __ldg(&adj[j + 1]);
        uint4 a = base[(size_t)s0 * 16 + lane];
        uint4 b = base[(size_t)s1 * 16 + lane];
        add8(acc0, a); add8(acc1, b);
    }
    if (j < jend) add8(acc0, base[(size_t)__ldg(&adj[j]) * 16 + lane]);
#pragma unroll
    for (int i = 0; i < 8; i++) acc0[i] += acc1[i];

    const float di = dinv[w];
    const int col = lane * 8;
    float o[8];
#pragma unroll
    for (int i = 0; i < 8; i++) o[i] = fmaf(acc0[i], di, bias[col + i]);

    if (FINAL) {
        const float4* xr = reinterpret_cast<const float4*>(xres + (size_t)w * DD + col);
        float4 x0 = xr[0], x1 = xr[1];
        o[0] += x0.x; o[1] += x0.y; o[2] += x0.z; o[3] += x0.w;
        o[4] += x1.x; o[5] += x1.y; o[6] += x1.z; o[7] += x1.w;
        float4* op = reinterpret_cast<float4*>(outf + (size_t)w * DD + col);
        op[0] = make_float4(o[0], o[1], o[2], o[3]);
        op[1] = make_float4(o[4], o[5], o[6], o[7]);
    } else {
        uint4 hv;
        uint32_t* hp = reinterpret_cast<uint32_t*>(&hv);
#pragma unroll
        for (int i = 0; i < 4; i++) {
            __half2 h2 = __floats2half2_rn(fmaxf(o[2 * i], 0.f), fmaxf(o[2 * i + 1], 0.f));
            hp[i] = *reinterpret_cast<uint32_t*>(&h2);
        }
        reinterpret_cast<uint4*>(outh)[(size_t)w * 16 + lane] = hv;
    }
}

// ---------------------------------------------------------------------------
extern "C" void kernel_launch(void* const* d_in, const int* in_sizes, int n_in,
                              void* d_out, int out_size) {
    const float* x  = (const float*)d_in[0];
    const int*   ei = (const int*)d_in[1];
    const float* W0 = (const float*)d_in[2];
    const float* b0 = (const float*)d_in[3];
    const float* W1 = (const float*)d_in[4];
    const float* b1 = (const float*)d_in[5];
    const float* W2 = (const float*)d_in[6];
    const float* b2 = (const float*)d_in[7];
    float* out = (float*)d_out;

    const int n = in_sizes[0] / DD;
    const int e = in_sizes[1] / 2;
    const int* src = ei;
    const int* dst = ei + e;

    float* d_dinv;
    __half *d_hws, *d_aggh, *d_wt;
    int *d_count, *d_rowptr, *d_cursor, *d_adj, *d_partials;
    cudaGetSymbolAddress((void**)&d_hws, g_hwsh);
    cudaGetSymbolAddress((void**)&d_aggh, g_aggh);
    cudaGetSymbolAddress((void**)&d_dinv, g_dinv);
    cudaGetSymbolAddress((void**)&d_count, g_count);
    cudaGetSymbolAddress((void**)&d_rowptr, g_rowptr);
    cudaGetSymbolAddress((void**)&d_cursor, g_cursor);
    cudaGetSymbolAddress((void**)&d_adj, g_adj);
    cudaGetSymbolAddress((void**)&d_partials, g_partials);
    cudaGetSymbolAddress((void**)&d_wt, g_wt);

    cudaFuncSetAttribute(k_gemm_mma<false>, cudaFuncAttributeMaxDynamicSharedMemorySize, SM_TOT);
    cudaFuncSetAttribute(k_gemm_mma<true>,  cudaFuncAttributeMaxDynamicSharedMemorySize, SM_TOT);

    const int TB = 256;
    const int nb_n = (n + TB - 1) / TB;
    const int nb_e = (e + TB - 1) / TB;
    const int nb_gemm = (n + 127) / 128;
    const int nchunks = (n + SCAN_B - 1) / SCAN_B;
    const long long agg_threads = (long long)n * 16;
    const int nb_agg = (int)((agg_threads + TB - 1) / TB);

    // CSR build + dinv
    k_zero<<<nb_n, TB>>>(d_count, n);
    k_count<<<nb_e, TB>>>(dst, d_count, e);
    k_scan_chunks<<<nchunks, SCAN_B>>>(d_count, d_rowptr, d_partials, d_dinv, n);
    k_scan_partials<<<1, 64>>>(d_partials, nchunks);
    k_scan_finish<<<nb_n, TB>>>(d_rowptr, d_cursor, d_partials, n, e);
    k_fill<<<nb_e, TB>>>(src, dst, d_cursor, d_adj, e);

    // W^T fp16 (all 3 layers, one launch)
    k_wprep<<<192, 256>>>(W0, W1, W2, d_wt);

    // Layer 0 (fp32 input x)
    k_gemm_mma<false><<<nb_gemm, 256, SM_TOT>>>(x, nullptr, d_wt, d_dinv, d_hws, n);
    k_aggregate<false><<<nb_agg, TB>>>(d_hws, d_rowptr, d_adj, d_dinv, b0, nullptr, d_aggh, nullptr, n);
    // Layer 1 (fp16 input, relu pre-applied)
    k_gemm_mma<true><<<nb_gemm, 256, SM_TOT>>>(nullptr, d_aggh, d_wt + DD * DD, d_dinv, d_hws, n);
    k_aggregate<false><<<nb_agg, TB>>>(d_hws, d_rowptr, d_adj, d_dinv, b1, nullptr, d_aggh, nullptr, n);
    // Layer 2 (fp16 input; +x residual fp32 -> d_out)
    k_gemm_mma<true><<<nb_gemm, 256, SM_TOT>>>(nullptr, d_aggh, d_wt + 2 * DD * DD, d_dinv, d_hws, n);
    k_aggregate<true><<<nb_agg, TB>>>(d_hws, d_rowptr, d_adj, d_dinv, b2, x, nullptr, out, n);
}